// round 12
// baseline (speedup 1.0000x reference)
#include <cuda_runtime.h>
#include <cuda_fp16.h>
#include <math.h>

typedef unsigned int       u32;
typedef unsigned long long u64;

#define T_TOK 4096
#define D_DIM 1024
#define I_DIM 4096
#define E_NUM 8
#define SLOTS (2 * T_TOK)

// ---------------- scratch (device globals; no runtime allocation) ----------
__device__ __half g_h[(size_t)T_TOK * D_DIM];                      // A for GEMM1
__device__ __half g_w1t[(size_t)E_NUM * I_DIM * D_DIM];            // [E][I][D]
__device__ __half g_w2t[(size_t)E_NUM * D_DIM * I_DIM];            // [E][D][I]
__device__ __half g_mid[(size_t)SLOTS * I_DIM];                    // A for GEMM2
__device__ float g_eout[(size_t)SLOTS * D_DIM];
__device__ int   g_sel[T_TOK * 2];
__device__ float g_wgt[T_TOK * 2];
__device__ int   g_slot[T_TOK * 2];
__device__ int   g_tok_of_slot[SLOTS];
__device__ int   g_counts[E_NUM];
__device__ int   g_cursor[E_NUM];
__device__ int   g_offsets[E_NUM];
// persistent-scheduler state
__device__ int   g_tile;
__device__ int   g_w2done;
__device__ int   g_ready[E_NUM * 32];
__device__ int   g_p1base[E_NUM + 1];
__device__ int   g_p2base[E_NUM + 1];
__device__ int   g_NT1, g_NT2;

#define NCONV 1024   // w2-conversion tiles: 8 e x 32 n-strips x 4 k-groups

// ---------------- PTX helpers ------------------------------------------------
__device__ __forceinline__ u32 smem_u32(const void* p) {
    u32 a;
    asm("{ .reg .u64 t; cvta.to.shared.u64 t, %1; cvt.u32.u64 %0, t; }"
        : "=r"(a) : "l"(p));
    return a;
}

#define CPA16(d, s) \
    asm volatile("cp.async.cg.shared.global [%0], [%1], 16;" \
                 :: "r"(d), "l"(s) : "memory")
#define CPA_COMMIT() asm volatile("cp.async.commit_group;" ::: "memory")
#define CPA_WAIT1()  asm volatile("cp.async.wait_group 1;" ::: "memory")
#define CPA_WAIT0()  asm volatile("cp.async.wait_group 0;" ::: "memory")

#define LDSM4(r0, r1, r2, r3, a) \
    asm volatile("ldmatrix.sync.aligned.m8n8.x4.shared.b16 {%0,%1,%2,%3}, [%4];" \
                 : "=r"(r0), "=r"(r1), "=r"(r2), "=r"(r3) : "r"(a))

#define MMA16816(c, a, b0, b1) \
    asm volatile("mma.sync.aligned.m16n8k16.row.col.f32.f16.f16.f32 " \
                 "{%0,%1,%2,%3}, {%4,%5,%6,%7}, {%8,%9}, {%0,%1,%2,%3};" \
                 : "+f"((c)[0]), "+f"((c)[1]), "+f"((c)[2]), "+f"((c)[3]) \
                 : "r"((a)[0]), "r"((a)[1]), "r"((a)[2]), "r"((a)[3]), \
                   "r"(b0), "r"(b1))

__device__ __forceinline__ float gelu_exact(float x) {
    return 0.5f * x * (1.0f + erff(x * 0.70710678118654752f));
}

__device__ __forceinline__ u32 packh2(float x, float y) {
    __half2 p = __floats2half2_rn(x, y);
    return *(u32*)&p;
}

// ---------------- 0: init ---------------------------------------------------
__global__ void init_kernel() {
    int i = threadIdx.x;
    if (i < E_NUM) { g_counts[i] = 0; g_cursor[i] = 0; }
    if (i == 0) { g_tile = 0; g_w2done = 0; }
    g_ready[i] = 0;    // 256 entries, blockDim = 256
}

// ---------------- 1: gating + h->fp16 (fused) --------------------------------
__global__ void gate_kernel(const float* __restrict__ h,
                            const float* __restrict__ gw) {
    const int t = blockIdx.x;
    const int tid = threadIdx.x;
    const int warp = tid >> 5, lane = tid & 31;
    __shared__ float row[D_DIM];
    __shared__ float lg[E_NUM];

    float4 v = ((const float4*)(h + (size_t)t * D_DIM))[tid];
    u32 p0 = packh2(v.x, v.y);
    u32 p1 = packh2(v.z, v.w);
    ((uint2*)g_h)[(size_t)t * (D_DIM / 4) + tid] = make_uint2(p0, p1);
    ((float4*)row)[tid] = v;
    __syncthreads();

    const float* gr = gw + (size_t)warp * D_DIM;
    float s = 0.f;
    for (int j = lane; j < D_DIM; j += 32) s += row[j] * gr[j];
    #pragma unroll
    for (int o = 16; o; o >>= 1) s += __shfl_xor_sync(0xffffffffu, s, o);
    if (lane == 0) lg[warp] = s;
    __syncthreads();
    if (tid == 0) {
        float m = lg[0];
        #pragma unroll
        for (int e = 1; e < E_NUM; e++) m = fmaxf(m, lg[e]);
        float p[E_NUM], den = 0.f;
        #pragma unroll
        for (int e = 0; e < E_NUM; e++) { p[e] = expf(lg[e] - m); den += p[e]; }
        float inv_den = 1.0f / den;
        #pragma unroll
        for (int e = 0; e < E_NUM; e++) p[e] *= inv_den;
        int i0 = 0;
        #pragma unroll
        for (int e = 1; e < E_NUM; e++) if (p[e] > p[i0]) i0 = e;
        int i1 = (i0 == 0) ? 1 : 0;
        #pragma unroll
        for (int e = 0; e < E_NUM; e++)
            if (e != i0 && e != i1 && p[e] > p[i1]) i1 = e;
        float w0 = p[i0], w1 = p[i1];
        float inv = 1.0f / (w0 + w1);
        g_sel[2 * t + 0] = i0; g_sel[2 * t + 1] = i1;
        g_wgt[2 * t + 0] = w0 * inv; g_wgt[2 * t + 1] = w1 * inv;
        atomicAdd(&g_counts[i0], 1);
        atomicAdd(&g_counts[i1], 1);
    }
}

// ---------------- 2: prefix sum + aux loss + tile bases ----------------------
__global__ void prefix_kernel(float* aux_out) {
    if (threadIdx.x == 0) {
        int acc = 0; float aux = 0.f;
        int a1 = 0, a2 = 0;
        #pragma unroll
        for (int e = 0; e < E_NUM; e++) {
            g_offsets[e] = acc; acc += g_counts[e];
            float u = (float)g_counts[e] / (float)T_TOK - 1.0f / (float)E_NUM;
            aux += u * u;
            g_p1base[e] = a1; g_p2base[e] = a2;
            int mt = (g_counts[e] + 127) / 128;
            a1 += mt * 32;   // 32 n-tiles of GEMM1 (I/128)
            a2 += mt * 8;    // 8  n-tiles of GEMM2 (D/128)
        }
        g_p1base[E_NUM] = a1; g_NT1 = a1;
        g_p2base[E_NUM] = a2; g_NT2 = a2;
        if (aux_out) *aux_out = aux / (float)E_NUM;
    }
}

// ---------------- 3: scatter ------------------------------------------------
__global__ void scatter_kernel() {
    int t = blockIdx.x * blockDim.x + threadIdx.x;
    if (t >= T_TOK) return;
    #pragma unroll
    for (int k = 0; k < 2; k++) {
        int e = g_sel[2 * t + k];
        int pos = atomicAdd(&g_cursor[e], 1);
        int s = g_offsets[e] + pos;
        g_tok_of_slot[s] = t;
        g_slot[2 * t + k] = s;
    }
}

// ---------------- 4: transpose + convert w1 to fp16 (side stream) ------------
__global__ void tsplit_w1_kernel(const float* __restrict__ W) {
    __shared__ float t[64][33];
    const int e = blockIdx.z;
    const int n0 = blockIdx.x * 32, k0 = blockIdx.y * 64;
    const int tx = threadIdx.x, ty = threadIdx.y;   // (32, 8)
    const float* Wp = W + (size_t)e * D_DIM * I_DIM + n0 + tx;
    #pragma unroll
    for (int j = 0; j < 8; j++)
        t[ty + 8 * j][tx] = Wp[(size_t)(k0 + ty + 8 * j) * I_DIM];
    __syncthreads();
    u32* oh = (u32*)g_w1t;
    #pragma unroll
    for (int j = 0; j < 4; j++) {
        const int n = ty + 8 * j;
        float x0 = t[2 * tx][n], x1 = t[2 * tx + 1][n];
        size_t o = ((size_t)e * I_DIM * D_DIM + (size_t)(n0 + n) * D_DIM + k0) / 2 + tx;
        oh[o] = packh2(x0, x1);
    }
}

// ---------------- 5: fused persistent kernel ---------------------------------
// Phases per tile counter: [first-wave GEMM1 | w2 conversion | rest GEMM1 | GEMM2]
#define ROWB   80
#define MATB   (128 * ROWB)       // 10240
#define STAGEB (2 * MATB)         // 20480
#define GSMEM_BYTES (2 * STAGEB)  // 40960

__device__ __forceinline__ void gemm_tile(int e, int m0, int n0, bool first,
                                          const float* __restrict__ bias,
                                          char* smem) {
    const int KD = first ? D_DIM : I_DIM;
    const int ND = first ? I_DIM : D_DIM;
    const int cnt = g_counts[e];
    const int base = g_offsets[e];
    const u32 sb = smem_u32(smem);

    const int tid  = threadIdx.x;
    const int lane = tid & 31, wid = tid >> 5;

    const int lrow = tid >> 1;
    const int lkh  = (tid & 1) * 16;
    int am = m0 + lrow; if (am >= cnt) am = cnt - 1;
    const __half* pa;
    if (first) {
        int tok = g_tok_of_slot[base + am];
        pa = g_h + (size_t)tok * KD;
    } else {
        pa = g_mid + (size_t)(base + am) * KD;
    }
    const __half* pb =
        (first ? g_w1t : g_w2t) + ((size_t)e * ND + n0 + lrow) * KD;
    const u32 doff = (u32)(lrow * ROWB + (tid & 1) * 32);

    float c[4][4][4];
    #pragma unroll
    for (int i = 0; i < 4; i++)
        #pragma unroll
        for (int f = 0; f < 4; f++)
            #pragma unroll
            for (int q = 0; q < 4; q++) c[i][f][q] = 0.f;

    const int wm = (wid & 1) * 64;
    const int wn = (wid >> 1) * 32;
    const int l15 = lane & 15;
    const int lk16 = (lane >> 4) * 16;

    const int NK = KD / 32;

    // prologue: stage 0
    {
        const __half* s0 = pa + lkh;
        const __half* s1 = pb + lkh;
        u32 d = sb + doff;
        CPA16(d,        s0); CPA16(d + 16,        s0 + 8);
        CPA16(d + MATB, s1); CPA16(d + MATB + 16, s1 + 8);
    }
    CPA_COMMIT();

    #pragma unroll 1
    for (int kc = 0; kc < NK; kc++) {
        if (kc + 1 < NK) {
            const int kt = (kc + 1) * 32;
            const __half* s0 = pa + kt + lkh;
            const __half* s1 = pb + kt + lkh;
            u32 d = sb + ((kc + 1) & 1) * STAGEB + doff;
            CPA16(d,        s0); CPA16(d + 16,        s0 + 8);
            CPA16(d + MATB, s1); CPA16(d + MATB + 16, s1 + 8);
            CPA_COMMIT();
            CPA_WAIT1();
        } else {
            CPA_COMMIT();
            CPA_WAIT0();
        }
        __syncthreads();

        const u32 stb = sb + (kc & 1) * STAGEB;
        const u32 Am = stb, Bm = stb + MATB;

        #pragma unroll
        for (int s = 0; s < 2; s++) {
            const u32 koff = (u32)(s * 32 + lk16);

            u32 bh[8];
            #pragma unroll
            for (int j = 0; j < 2; j++) {
                u32 rb = (u32)((wn + j * 16 + l15) * ROWB) + koff;
                LDSM4(bh[j*4+0], bh[j*4+1], bh[j*4+2], bh[j*4+3], Bm + rb);
            }
            u32 ah[4][4];
            #pragma unroll
            for (int i = 0; i < 4; i++) {
                u32 ra = (u32)((wm + i * 16 + l15) * ROWB) + koff;
                LDSM4(ah[i][0], ah[i][1], ah[i][2], ah[i][3], Am + ra);
            }
            #pragma unroll
            for (int i = 0; i < 4; i++)
                #pragma unroll
                for (int f = 0; f < 4; f++) {
                    int j = f >> 1, r = f & 1;
                    MMA16816(c[i][f], ah[i], bh[j*4 + r], bh[j*4 + r + 2]);
                }
        }
        __syncthreads();
    }

    // epilogue
    #pragma unroll
    for (int f = 0; f < 4; f++) {
        const int ncol = n0 + wn + f * 8 + (lane & 3) * 2;
        const float bz0 = bias[(size_t)e * ND + ncol];
        const float bz1 = bias[(size_t)e * ND + ncol + 1];
        #pragma unroll
        for (int i = 0; i < 4; i++) {
            const int mr0 = m0 + wm + i * 16 + (lane >> 2);
            #pragma unroll
            for (int half = 0; half < 2; half++) {
                const int m = mr0 + half * 8;
                if (m >= cnt) continue;
                float v0 = c[i][f][half * 2 + 0] + bz0;
                float v1 = c[i][f][half * 2 + 1] + bz1;
                const size_t off = (size_t)(base + m) * ND + ncol;
                if (first) {
                    float y0 = gelu_exact(v0), y1 = gelu_exact(v1);
                    *(u32*)(g_mid + off) = packh2(y0, y1);
                } else {
                    *(float2*)(g_eout + off) = make_float2(v0, v1);
                }
            }
        }
    }
}

__device__ __forceinline__ void conv_tile(int c, const float* __restrict__ w2,
                                          char* smem) {
    float (*t)[33] = (float (*)[33])smem;   // 64x33 floats = 8448 B
    const int e  = c >> 7;
    const int r  = c & 127;
    const int n0 = (r >> 2) * 32;
    const int k0base = (r & 3) * 1024;
    const int tx = threadIdx.x & 31, ty = threadIdx.x >> 5;   // ty 0..7
    const float* Wp = w2 + (size_t)e * I_DIM * D_DIM + n0 + tx;
    u32* oh = (u32*)g_w2t;
    #pragma unroll 1
    for (int j = 0; j < 16; j++) {
        const int k0 = k0base + j * 64;
        #pragma unroll
        for (int jj = 0; jj < 8; jj++)
            t[ty + 8 * jj][tx] = Wp[(size_t)(k0 + ty + 8 * jj) * D_DIM];
        __syncthreads();
        #pragma unroll
        for (int jj = 0; jj < 4; jj++) {
            const int n = ty + 8 * jj;
            float x0 = t[2 * tx][n], x1 = t[2 * tx + 1][n];
            size_t o = ((size_t)e * D_DIM * I_DIM + (size_t)(n0 + n) * I_DIM + k0) / 2 + tx;
            oh[o] = packh2(x0, x1);
        }
        __syncthreads();
    }
}

__global__ void __launch_bounds__(256, 2)
moe_fused_kernel(const float* __restrict__ w2,
                 const float* __restrict__ b1,
                 const float* __restrict__ b2) {
    extern __shared__ char smem[];
    __shared__ int s_tile;
    const int tid = threadIdx.x;
    const int NT1 = g_NT1, NT2 = g_NT2;
    const int W = min((int)gridDim.x, NT1);     // first-wave GEMM1 count
    const int total = NT1 + NCONV + NT2;

    for (;;) {
        if (tid == 0) s_tile = atomicAdd(&g_tile, 1);
        __syncthreads();
        const int t = s_tile;
        __syncthreads();
        if (t >= total) break;

        if (t < W) {
            // GEMM1 tile (first wave)
            int idx = t, e = 0;
            while (idx >= g_p1base[e + 1]) e++;
            int local = idx - g_p1base[e];
            int mt = local >> 5, nt = local & 31;
            gemm_tile(e, mt * 128, nt * 128, true, b1, smem);
            __threadfence(); __syncthreads();
            if (tid == 0) atomicAdd(&g_ready[e * 32 + mt], 1);
        } else if (t < W + NCONV) {
            // w2 conversion tile (overlaps GEMM1 middle waves)
            conv_tile(t - W, w2, smem);
            __threadfence(); __syncthreads();
            if (tid == 0) atomicAdd(&g_w2done, 1);
        } else if (t < NCONV + NT1) {
            // GEMM1 tile (rest)
            int idx = t - NCONV, e = 0;
            while (idx >= g_p1base[e + 1]) e++;
            int local = idx - g_p1base[e];
            int mt = local >> 5, nt = local & 31;
            gemm_tile(e, mt * 128, nt * 128, true, b1, smem);
            __threadfence(); __syncthreads();
            if (tid == 0) atomicAdd(&g_ready[e * 32 + mt], 1);
        } else {
            // GEMM2 tile: wait for w2t + its mid row-block
            int idx = t - NCONV - NT1, e = 0;
            while (idx >= g_p2base[e + 1]) e++;
            int local = idx - g_p2base[e];
            int mt = local >> 3, nt = local & 7;
            if (tid == 0) {
                while (atomicAdd(&g_w2done, 0) < NCONV) __nanosleep(128);
                while (atomicAdd(&g_ready[e * 32 + mt], 0) < 32) __nanosleep(128);
                __threadfence();
            }
            __syncthreads();
            gemm_tile(e, mt * 128, nt * 128, false, b2, smem);
        }
        __syncthreads();
    }
}

// ---------------- 6: combine + residual + LayerNorm -------------------------
__device__ __forceinline__ float blockReduceSum256(float v) {
    __shared__ float sm[8];
    #pragma unroll
    for (int o = 16; o; o >>= 1) v += __shfl_xor_sync(0xffffffffu, v, o);
    if ((threadIdx.x & 31) == 0) sm[threadIdx.x >> 5] = v;
    __syncthreads();
    float r = sm[threadIdx.x & 7];
    #pragma unroll
    for (int o = 4; o; o >>= 1) r += __shfl_xor_sync(0xffffffffu, r, o);
    __syncthreads();
    return r;
}

__global__ void combine_ln_kernel(const float* __restrict__ h,
                                  const float* __restrict__ mask,
                                  const float* __restrict__ gamma,
                                  const float* __restrict__ beta,
                                  float* __restrict__ out) {
    const int t = blockIdx.x;
    const float mk = mask[t];
    const int s0 = g_slot[2 * t + 0], s1 = g_slot[2 * t + 1];
    const float w0 = g_wgt[2 * t + 0], w1 = g_wgt[2 * t + 1];
    const float* e0 = g_eout + (size_t)s0 * D_DIM;
    const float* e1 = g_eout + (size_t)s1 * D_DIM;
    const float* hr = h + (size_t)t * D_DIM;

    float y[4];
    float s = 0.f;
    #pragma unroll
    for (int j = 0; j < 4; j++) {
        int d = threadIdx.x + j * 256;
        y[j] = hr[d] + mk * (w0 * e0[d] + w1 * e1[d]);
        s += y[j];
    }
    float mean = blockReduceSum256(s) * (1.0f / D_DIM);
    float vs = 0.f;
    #pragma unroll
    for (int j = 0; j < 4; j++) { float cdev = y[j] - mean; vs += cdev * cdev; }
    float var = blockReduceSum256(vs) * (1.0f / D_DIM);
    float rs = rsqrtf(var + 1e-5f);
    #pragma unroll
    for (int j = 0; j < 4; j++) {
        int d = threadIdx.x + j * 256;
        out[(size_t)t * D_DIM + d] = (y[j] - mean) * rs * gamma[d] + beta[d];
    }
}

// ---------------- launch -----------------------------------------------------
extern "C" void kernel_launch(void* const* d_in, const int* in_sizes, int n_in,
                              void* d_out, int out_size) {
    const float* h     = (const float*)d_in[0];
    const float* mask  = (const float*)d_in[1];
    const float* gw    = (const float*)d_in[2];
    const float* w1    = (const float*)d_in[3];
    const float* b1    = (const float*)d_in[4];
    const float* w2    = (const float*)d_in[5];
    const float* b2    = (const float*)d_in[6];
    const float* gamma = (const float*)d_in[7];
    const float* beta  = (const float*)d_in[8];
    float* out = (float*)d_out;

    float* aux_ptr = (out_size > T_TOK * D_DIM) ? (out + (size_t)T_TOK * D_DIM)
                                                : nullptr;

    // one-time host-side setup (no device memory)
    static cudaStream_t s_side = nullptr;
    static cudaEvent_t ev_start, ev_w1;
    static int grid_persist = 0;
    if (!s_side) {
        cudaStreamCreateWithFlags(&s_side, cudaStreamNonBlocking);
        cudaEventCreateWithFlags(&ev_start, cudaEventDisableTiming);
        cudaEventCreateWithFlags(&ev_w1, cudaEventDisableTiming);
        int dev = 0, nsm = 148;
        cudaGetDevice(&dev);
        cudaDeviceGetAttribute(&nsm, cudaDevAttrMultiProcessorCount, dev);
        grid_persist = 2 * nsm;
        cudaFuncSetAttribute(moe_fused_kernel,
                             cudaFuncAttributeMaxDynamicSharedMemorySize, GSMEM_BYTES);
    }

    // side stream: w1 conversion overlaps the routing chain
    cudaEventRecord(ev_start, 0);
    cudaStreamWaitEvent(s_side, ev_start, 0);
    { dim3 g(I_DIM / 32, D_DIM / 64, E_NUM);
      tsplit_w1_kernel<<<g, dim3(32, 8), 0, s_side>>>(w1); }
    cudaEventRecord(ev_w1, s_side);

    // main stream: routing chain
    init_kernel<<<1, 256>>>();
    gate_kernel<<<T_TOK, 256>>>(h, gw);
    prefix_kernel<<<1, 1>>>(aux_ptr);
    scatter_kernel<<<(T_TOK + 255) / 256, 256>>>();

    // fused persistent GEMM1 + w2-conversion + GEMM2
    cudaStreamWaitEvent(0, ev_w1, 0);
    moe_fused_kernel<<<grid_persist, 256, GSMEM_BYTES>>>(w2, b1, b2);

    combine_ln_kernel<<<T_TOK, 256>>>(h, mask, gamma, beta, out);
}

// round 13
// speedup vs baseline: 1.1168x; 1.1168x over previous
#include <cuda_runtime.h>
#include <cuda_fp16.h>
#include <math.h>

typedef unsigned int       u32;
typedef unsigned long long u64;

#define T_TOK 4096
#define D_DIM 1024
#define I_DIM 4096
#define E_NUM 8
#define ECAP  4096            // padded per-expert slot capacity

// ---------------- scratch (device globals; no runtime allocation) ----------
__device__ __half g_h[(size_t)T_TOK * D_DIM];                       // A for GEMM1
__device__ __half g_w1t[(size_t)E_NUM * I_DIM * D_DIM];             // [E][I][D]
__device__ __half g_w2t[(size_t)E_NUM * D_DIM * I_DIM];             // [E][D][I]
__device__ __half g_mid[(size_t)E_NUM * ECAP * I_DIM];              // A for GEMM2 (padded)
__device__ float g_eout[(size_t)E_NUM * ECAP * D_DIM];              // padded
__device__ int   g_sel[T_TOK * 2];
__device__ float g_wgt[T_TOK * 2];
__device__ int   g_slot[T_TOK * 2];
__device__ int   g_tok_of_slot[E_NUM * ECAP];
__device__ int   g_counts[E_NUM];
__device__ int   g_cursor[E_NUM];

// ---------------- PTX helpers ------------------------------------------------
__device__ __forceinline__ u32 smem_u32(const void* p) {
    u32 a;
    asm("{ .reg .u64 t; cvta.to.shared.u64 t, %1; cvt.u32.u64 %0, t; }"
        : "=r"(a) : "l"(p));
    return a;
}

#define CPA16(d, s) \
    asm volatile("cp.async.cg.shared.global [%0], [%1], 16;" \
                 :: "r"(d), "l"(s) : "memory")
#define CPA_COMMIT() asm volatile("cp.async.commit_group;" ::: "memory")
#define CPA_WAIT1()  asm volatile("cp.async.wait_group 1;" ::: "memory")
#define CPA_WAIT0()  asm volatile("cp.async.wait_group 0;" ::: "memory")

#define LDSM4(r0, r1, r2, r3, a) \
    asm volatile("ldmatrix.sync.aligned.m8n8.x4.shared.b16 {%0,%1,%2,%3}, [%4];" \
                 : "=r"(r0), "=r"(r1), "=r"(r2), "=r"(r3) : "r"(a))

#define MMA16816(c, a, b0, b1) \
    asm volatile("mma.sync.aligned.m16n8k16.row.col.f32.f16.f16.f32 " \
                 "{%0,%1,%2,%3}, {%4,%5,%6,%7}, {%8,%9}, {%0,%1,%2,%3};" \
                 : "+f"((c)[0]), "+f"((c)[1]), "+f"((c)[2]), "+f"((c)[3]) \
                 : "r"((a)[0]), "r"((a)[1]), "r"((a)[2]), "r"((a)[3]), \
                   "r"(b0), "r"(b1))

__device__ __forceinline__ float gelu_exact(float x) {
    return 0.5f * x * (1.0f + erff(x * 0.70710678118654752f));
}

__device__ __forceinline__ u32 packh2(float x, float y) {
    __half2 p = __floats2half2_rn(x, y);
    return *(u32*)&p;
}

// ---------------- 0: init ---------------------------------------------------
__global__ void init_kernel() {
    int i = threadIdx.x;
    if (i < E_NUM) { g_counts[i] = 0; g_cursor[i] = 0; }
}

// ---------------- 1: gating + h->fp16 (fused) --------------------------------
__global__ void gate_kernel(const float* __restrict__ h,
                            const float* __restrict__ gw) {
    const int t = blockIdx.x;
    const int tid = threadIdx.x;
    const int warp = tid >> 5, lane = tid & 31;
    __shared__ float row[D_DIM];
    __shared__ float lg[E_NUM];

    float4 v = ((const float4*)(h + (size_t)t * D_DIM))[tid];
    u32 p0 = packh2(v.x, v.y);
    u32 p1 = packh2(v.z, v.w);
    ((uint2*)g_h)[(size_t)t * (D_DIM / 4) + tid] = make_uint2(p0, p1);
    ((float4*)row)[tid] = v;
    __syncthreads();

    // vectorized dot: warp e computes <row, gw[e]> with float4 loads
    const float4* rowv = (const float4*)row;
    const float4* grv  = (const float4*)(gw + (size_t)warp * D_DIM);
    float s = 0.f;
    #pragma unroll
    for (int j = 0; j < 8; j++) {
        float4 a = rowv[lane + 32 * j];
        float4 b = grv[lane + 32 * j];
        s += a.x * b.x + a.y * b.y + a.z * b.z + a.w * b.w;
    }
    #pragma unroll
    for (int o = 16; o; o >>= 1) s += __shfl_xor_sync(0xffffffffu, s, o);
    if (lane == 0) lg[warp] = s;
    __syncthreads();
    if (tid == 0) {
        float m = lg[0];
        #pragma unroll
        for (int e = 1; e < E_NUM; e++) m = fmaxf(m, lg[e]);
        float p[E_NUM], den = 0.f;
        #pragma unroll
        for (int e = 0; e < E_NUM; e++) { p[e] = expf(lg[e] - m); den += p[e]; }
        float inv_den = 1.0f / den;
        #pragma unroll
        for (int e = 0; e < E_NUM; e++) p[e] *= inv_den;
        int i0 = 0;
        #pragma unroll
        for (int e = 1; e < E_NUM; e++) if (p[e] > p[i0]) i0 = e;
        int i1 = (i0 == 0) ? 1 : 0;
        #pragma unroll
        for (int e = 0; e < E_NUM; e++)
            if (e != i0 && e != i1 && p[e] > p[i1]) i1 = e;
        float w0 = p[i0], w1 = p[i1];
        float inv = 1.0f / (w0 + w1);
        g_sel[2 * t + 0] = i0; g_sel[2 * t + 1] = i1;
        g_wgt[2 * t + 0] = w0 * inv; g_wgt[2 * t + 1] = w1 * inv;
        atomicAdd(&g_counts[i0], 1);
        atomicAdd(&g_counts[i1], 1);
    }
}

// ---------------- 2: scatter (padded slots) + aux loss -----------------------
__global__ void scatter_kernel(float* aux_out) {
    int t = blockIdx.x * blockDim.x + threadIdx.x;
    if (t == 0 && aux_out) {
        float aux = 0.f;
        #pragma unroll
        for (int e = 0; e < E_NUM; e++) {
            float u = (float)g_counts[e] / (float)T_TOK - 1.0f / (float)E_NUM;
            aux += u * u;
        }
        *aux_out = aux / (float)E_NUM;
    }
    if (t >= T_TOK) return;
    #pragma unroll
    for (int k = 0; k < 2; k++) {
        int e = g_sel[2 * t + k];
        int pos = atomicAdd(&g_cursor[e], 1);
        int s = (e << 12) + pos;           // e * ECAP + pos
        g_tok_of_slot[s] = t;
        g_slot[2 * t + k] = s;
    }
}

// ---------------- 3: transpose + convert weights to fp16 --------------------
// W [E][KDIM][NDIM] fp32 -> [E][NDIM][KDIM] fp16
template <bool W1>
__global__ void tsplit_kernel(const float* __restrict__ W) {
    const int KDIM = W1 ? D_DIM : I_DIM;
    const int NDIM = W1 ? I_DIM : D_DIM;
    __shared__ float t[64][33];
    const int e = blockIdx.z;
    const int n0 = blockIdx.x * 32, k0 = blockIdx.y * 64;
    const int tx = threadIdx.x, ty = threadIdx.y;   // (32, 8)
    const float* Wp = W + (size_t)e * KDIM * NDIM + n0 + tx;
    #pragma unroll
    for (int j = 0; j < 8; j++)
        t[ty + 8 * j][tx] = Wp[(size_t)(k0 + ty + 8 * j) * NDIM];
    __syncthreads();
    u32* oh = (u32*)(W1 ? g_w1t : g_w2t);
    #pragma unroll
    for (int j = 0; j < 4; j++) {
        const int n = ty + 8 * j;
        float x0 = t[2 * tx][n], x1 = t[2 * tx + 1][n];
        size_t o = ((size_t)e * NDIM * KDIM + (size_t)(n0 + n) * KDIM + k0) / 2 + tx;
        oh[o] = packh2(x0, x1);
    }
}

// ---------------- 4/5: expert GEMMs via fp16 mma.sync (R11 config) -----------
// C = A_f16 * B_f16 (fp32 accum). Block tile 128x128x32, 8 warps (2m x 4n).
// 2 stages x 2 matrices x 128 rows x 80B; compile-time stage parity.
#define ROWB   80
#define MATB   (128 * ROWB)       // 10240
#define STAGEB (2 * MATB)         // 20480
#define GSMEM_BYTES (2 * STAGEB)  // 40960

template <int KD, int ND, bool FIRST>
__global__ void __launch_bounds__(256, 2)
mma_gemm_kernel(const float* __restrict__ bias) {
    const int e = blockIdx.z;
    const int cnt = g_counts[e];
    const int m0 = blockIdx.x * 128;
    if (m0 >= cnt) return;
    const int base = e << 12;            // e * ECAP
    const int n0 = blockIdx.y * 128;

    extern __shared__ char smem[];
    const u32 sb = smem_u32(smem);

    const int tid  = threadIdx.x;
    const int lane = tid & 31, wid = tid >> 5;

    // ---- loader mapping: thread -> (row 0..127, k-half 0/1) ----
    const int lrow = tid >> 1;
    const int lkh  = (tid & 1) * 16;
    int am = m0 + lrow; if (am >= cnt) am = cnt - 1;
    const __half* pa;
    if (FIRST) {
        int tok = g_tok_of_slot[base + am];
        pa = g_h + (size_t)tok * KD;
    } else {
        pa = g_mid + (size_t)(base + am) * KD;
    }
    const __half* pb =
        (FIRST ? g_w1t : g_w2t) + ((size_t)e * ND + n0 + lrow) * KD;
    const u32 doff = (u32)(lrow * ROWB + (tid & 1) * 32);

    float c[4][4][4];
    #pragma unroll
    for (int i = 0; i < 4; i++)
        #pragma unroll
        for (int f = 0; f < 4; f++)
            #pragma unroll
            for (int q = 0; q < 4; q++) c[i][f][q] = 0.f;

    const int wm = (wid & 1) * 64;
    const int wn = (wid >> 1) * 32;
    const int l15 = lane & 15;
    const int lk16 = (lane >> 4) * 16;

    const int NK = KD / 32;

    // prologue: stage 0
    {
        const __half* s0 = pa + lkh;
        const __half* s1 = pb + lkh;
        u32 d = sb + doff;
        CPA16(d,        s0); CPA16(d + 16,        s0 + 8);
        CPA16(d + MATB, s1); CPA16(d + MATB + 16, s1 + 8);
    }
    CPA_COMMIT();

    #pragma unroll 1
    for (int kc = 0; kc < NK; kc++) {
        if (kc + 1 < NK) {
            const int kt = (kc + 1) * 32;
            const __half* s0 = pa + kt + lkh;
            const __half* s1 = pb + kt + lkh;
            u32 d = sb + ((kc + 1) & 1) * STAGEB + doff;
            CPA16(d,        s0); CPA16(d + 16,        s0 + 8);
            CPA16(d + MATB, s1); CPA16(d + MATB + 16, s1 + 8);
            CPA_COMMIT();
            CPA_WAIT1();
        } else {
            CPA_COMMIT();
            CPA_WAIT0();
        }
        __syncthreads();

        const u32 stb = sb + (kc & 1) * STAGEB;
        const u32 Am = stb, Bm = stb + MATB;

        #pragma unroll
        for (int s = 0; s < 2; s++) {
            const u32 koff = (u32)(s * 32 + lk16);

            u32 bh[8];
            #pragma unroll
            for (int j = 0; j < 2; j++) {
                u32 rb = (u32)((wn + j * 16 + l15) * ROWB) + koff;
                LDSM4(bh[j*4+0], bh[j*4+1], bh[j*4+2], bh[j*4+3], Bm + rb);
            }
            u32 ah[4][4];
            #pragma unroll
            for (int i = 0; i < 4; i++) {
                u32 ra = (u32)((wm + i * 16 + l15) * ROWB) + koff;
                LDSM4(ah[i][0], ah[i][1], ah[i][2], ah[i][3], Am + ra);
            }
            #pragma unroll
            for (int i = 0; i < 4; i++)
                #pragma unroll
                for (int f = 0; f < 4; f++) {
                    int j = f >> 1, r = f & 1;
                    MMA16816(c[i][f], ah[i], bh[j*4 + r], bh[j*4 + r + 2]);
                }
        }
        __syncthreads();
    }

    // ---- epilogue ----
    #pragma unroll
    for (int f = 0; f < 4; f++) {
        const int ncol = n0 + wn + f * 8 + (lane & 3) * 2;
        const float bz0 = bias[(size_t)e * ND + ncol];
        const float bz1 = bias[(size_t)e * ND + ncol + 1];
        #pragma unroll
        for (int i = 0; i < 4; i++) {
            const int mr0 = m0 + wm + i * 16 + (lane >> 2);
            #pragma unroll
            for (int half = 0; half < 2; half++) {
                const int m = mr0 + half * 8;
                if (m >= cnt) continue;
                float v0 = c[i][f][half * 2 + 0] + bz0;
                float v1 = c[i][f][half * 2 + 1] + bz1;
                const size_t off = (size_t)(base + m) * ND + ncol;
                if (FIRST) {
                    float y0 = gelu_exact(v0), y1 = gelu_exact(v1);
                    *(u32*)(g_mid + off) = packh2(y0, y1);
                } else {
                    *(float2*)(g_eout + off) = make_float2(v0, v1);
                }
            }
        }
    }
}

// ---------------- 6: combine + residual + LayerNorm -------------------------
__device__ __forceinline__ float blockReduceSum256(float v) {
    __shared__ float sm[8];
    #pragma unroll
    for (int o = 16; o; o >>= 1) v += __shfl_xor_sync(0xffffffffu, v, o);
    if ((threadIdx.x & 31) == 0) sm[threadIdx.x >> 5] = v;
    __syncthreads();
    float r = sm[threadIdx.x & 7];
    #pragma unroll
    for (int o = 4; o; o >>= 1) r += __shfl_xor_sync(0xffffffffu, r, o);
    __syncthreads();
    return r;
}

__global__ void combine_ln_kernel(const float* __restrict__ h,
                                  const float* __restrict__ mask,
                                  const float* __restrict__ gamma,
                                  const float* __restrict__ beta,
                                  float* __restrict__ out) {
    const int t = blockIdx.x;
    const float mk = mask[t];
    const int s0 = g_slot[2 * t + 0], s1 = g_slot[2 * t + 1];
    const float w0 = g_wgt[2 * t + 0], w1 = g_wgt[2 * t + 1];
    const float* e0 = g_eout + (size_t)s0 * D_DIM;
    const float* e1 = g_eout + (size_t)s1 * D_DIM;
    const float* hr = h + (size_t)t * D_DIM;

    float y[4];
    float s = 0.f;
    #pragma unroll
    for (int j = 0; j < 4; j++) {
        int d = threadIdx.x + j * 256;
        y[j] = hr[d] + mk * (w0 * e0[d] + w1 * e1[d]);
        s += y[j];
    }
    float mean = blockReduceSum256(s) * (1.0f / D_DIM);
    float vs = 0.f;
    #pragma unroll
    for (int j = 0; j < 4; j++) { float cdev = y[j] - mean; vs += cdev * cdev; }
    float var = blockReduceSum256(vs) * (1.0f / D_DIM);
    float rs = rsqrtf(var + 1e-5f);
    #pragma unroll
    for (int j = 0; j < 4; j++) {
        int d = threadIdx.x + j * 256;
        out[(size_t)t * D_DIM + d] = (y[j] - mean) * rs * gamma[d] + beta[d];
    }
}

// ---------------- launch -----------------------------------------------------
extern "C" void kernel_launch(void* const* d_in, const int* in_sizes, int n_in,
                              void* d_out, int out_size) {
    const float* h     = (const float*)d_in[0];
    const float* mask  = (const float*)d_in[1];
    const float* gw    = (const float*)d_in[2];
    const float* w1    = (const float*)d_in[3];
    const float* b1    = (const float*)d_in[4];
    const float* w2    = (const float*)d_in[5];
    const float* b2    = (const float*)d_in[6];
    const float* gamma = (const float*)d_in[7];
    const float* beta  = (const float*)d_in[8];
    float* out = (float*)d_out;

    float* aux_ptr = (out_size > T_TOK * D_DIM) ? (out + (size_t)T_TOK * D_DIM)
                                                : nullptr;

    // one-time host-side setup (no device memory)
    static cudaStream_t s_side = nullptr;
    static cudaEvent_t ev_start, ev_w1, ev_w2;
    if (!s_side) {
        cudaStreamCreateWithFlags(&s_side, cudaStreamNonBlocking);
        cudaEventCreateWithFlags(&ev_start, cudaEventDisableTiming);
        cudaEventCreateWithFlags(&ev_w1, cudaEventDisableTiming);
        cudaEventCreateWithFlags(&ev_w2, cudaEventDisableTiming);
        cudaFuncSetAttribute(mma_gemm_kernel<D_DIM, I_DIM, true>,
                             cudaFuncAttributeMaxDynamicSharedMemorySize, GSMEM_BYTES);
        cudaFuncSetAttribute(mma_gemm_kernel<I_DIM, D_DIM, false>,
                             cudaFuncAttributeMaxDynamicSharedMemorySize, GSMEM_BYTES);
    }

    // fork side stream: weight conversions overlap routing chain + GEMM1 gaps
    cudaEventRecord(ev_start, 0);
    cudaStreamWaitEvent(s_side, ev_start, 0);
    { dim3 g(I_DIM / 32, D_DIM / 64, E_NUM);
      tsplit_kernel<true><<<g, dim3(32, 8), 0, s_side>>>(w1); }
    cudaEventRecord(ev_w1, s_side);
    { dim3 g(D_DIM / 32, I_DIM / 64, E_NUM);
      tsplit_kernel<false><<<g, dim3(32, 8), 0, s_side>>>(w2); }
    cudaEventRecord(ev_w2, s_side);

    // main stream: routing chain (prefix kernel eliminated)
    init_kernel<<<1, 32>>>();
    gate_kernel<<<T_TOK, 256>>>(h, gw);
    scatter_kernel<<<(T_TOK + 255) / 256, 256>>>(aux_ptr);

    // GEMM1 needs w1t
    cudaStreamWaitEvent(0, ev_w1, 0);
    { dim3 g(T_TOK / 128, I_DIM / 128, E_NUM);
      mma_gemm_kernel<D_DIM, I_DIM, true><<<g, 256, GSMEM_BYTES>>>(b1); }

    // GEMM2 needs w2t
    cudaStreamWaitEvent(0, ev_w2, 0);
    { dim3 g(T_TOK / 128, D_DIM / 128, E_NUM);
      mma_gemm_kernel<I_DIM, D_DIM, false><<<g, 256, GSMEM_BYTES>>>(b2); }

    combine_ln_kernel<<<T_TOK, 256>>>(h, mask, gamma, beta, out);
}